// round 15
// baseline (speedup 1.0000x reference)
#include <cuda_runtime.h>
#include <cuda_bf16.h>
#include <cuda_fp16.h>
#include <cstdint>
#include <math.h>

#define NB 2
#define NS 2048
#define ND 2048
#define NH 16
#define HD 128
#define NM (NB*NS)   // 4096 rows

// ---- scratch (static device arrays; no allocation allowed) ----
__device__ __half g_whf[4ll*ND*ND];              // W^T fp16, [N][K] K-major
__device__ __half g_qraw[(long long)NM*ND];      // Q proj fp16 (pre-rope)
__device__ __half g_kraw[(long long)NM*ND];      // K proj fp16 (pre-rope)
__device__ __half g_of[(long long)NM*ND];        // attention O fp16
__device__ __half g_qf[(long long)NM*ND];        // roped Q fp16 (scaled)
__device__ __half g_kf[(long long)NM*ND];        // roped K fp16
__device__ __half g_vf[(long long)NM*ND];        // V proj fp16
__device__ float  g_tab[NS*64*2];                // rope (cos,sin) table

__device__ __forceinline__ uint32_t smem_u32(const void* p) {
    uint32_t a;
    asm("{ .reg .u64 t; cvta.to.shared.u64 t, %1; cvt.u32.u64 %0, t; }"
        : "=r"(a) : "l"(p));
    return a;
}

// ---- base-target tensor core primitives (sm_80-class, valid on compute_103) ----
#define LDSM4(r, addr) \
    asm volatile("ldmatrix.sync.aligned.m8n8.x4.shared.b16 {%0,%1,%2,%3}, [%4];" \
        : "=r"((r)[0]), "=r"((r)[1]), "=r"((r)[2]), "=r"((r)[3]) : "r"(addr))

#define LDSM4T(r, addr) \
    asm volatile("ldmatrix.sync.aligned.m8n8.x4.trans.shared.b16 {%0,%1,%2,%3}, [%4];" \
        : "=r"((r)[0]), "=r"((r)[1]), "=r"((r)[2]), "=r"((r)[3]) : "r"(addr))

#define MMA16816H(d, a, b) \
    asm volatile("mma.sync.aligned.m16n8k16.row.col.f32.f16.f16.f32 " \
        "{%0,%1,%2,%3}, {%4,%5,%6,%7}, {%8,%9}, {%0,%1,%2,%3};" \
        : "+f"((d)[0]), "+f"((d)[1]), "+f"((d)[2]), "+f"((d)[3]) \
        : "r"((a)[0]), "r"((a)[1]), "r"((a)[2]), "r"((a)[3]), \
          "r"((b)[0]), "r"((b)[1]))

#define CP_ASYNC16(dst, src) \
    asm volatile("cp.async.cg.shared.global [%0], [%1], 16;" \
                 :: "r"(dst), "l"(src) : "memory")
#define CP_COMMIT()  asm volatile("cp.async.commit_group;" ::: "memory")
#define CP_WAIT1()   asm volatile("cp.async.wait_group 1;" ::: "memory")
#define CP_WAIT0()   asm volatile("cp.async.wait_group 0;" ::: "memory")

__device__ __forceinline__ uint32_t f16x2_pack(float lo, float hi) {
    __half2 v = __floats2half2_rn(lo, hi);
    return *reinterpret_cast<uint32_t*>(&v);
}

// ============================================================================
// conv_w_all: 4 weight matrices, one launch (z selects). Transpose to [N][K].
// ============================================================================
__global__ void conv_w_all_kernel(const float* __restrict__ W0,
                                  const float* __restrict__ W1,
                                  const float* __restrict__ W2,
                                  const float* __restrict__ W3,
                                  __half* __restrict__ Wt)
{
    const float* Wz = (blockIdx.z == 0) ? W0 : (blockIdx.z == 1) ? W1
                    : (blockIdx.z == 2) ? W2 : W3;
    __half* Wtz = Wt + (long long)blockIdx.z * ND * ND;
    __shared__ float t[32][33];
    int n0 = blockIdx.x * 32, k0 = blockIdx.y * 32;
    int tx = threadIdx.x, ty = threadIdx.y;
    for (int r = ty; r < 32; r += 8)
        t[r][tx] = Wz[(long long)(k0 + r) * ND + n0 + tx];
    __syncthreads();
    for (int r = ty; r < 32; r += 8)
        Wtz[(long long)(n0 + r) * ND + k0 + tx] = __float2half_rn(t[tx][r]);
}

// ============================================================================
// tab_kernel: rope (cos,sin) table, [s][i] -> (cos, sin)
// ============================================================================
__global__ void tab_kernel(float* __restrict__ tab)
{
    int idx = blockIdx.x * blockDim.x + threadIdx.x;   // NS*64
    int i = idx & 63, s = idx >> 6;
    float ang = (float)s * powf(10000.0f, -(float)i / 64.0f);
    float sn, cs;
    sincosf(ang, &sn, &cs);
    tab[idx*2]   = cs;
    tab[idx*2+1] = sn;
}

// ============================================================================
// 1-pass fp16 GEMM body (templated on A dtype):
//   AF32=true : A read as fp32, converted to fp16 fragments in-kernel (LDS+cvt)
//   AF32=false: A read as fp16, ldmatrix fragments
// C = A @ W^T(f16) + bias. Outputs fp32 C and/or fp16 Cf.
// CTA 128x128, 8 warps (warp tile 64x32), K-chunk 32, double buffer.
// ============================================================================
template <bool AF32>
__device__ __forceinline__
void gemm_f16_body(char* dsm,
                   const void* __restrict__ Avoid,
                   const __half* __restrict__ Wf,
                   const float* __restrict__ bias,
                   float* __restrict__ C,
                   __half* __restrict__ Cf,
                   int m0, int n0)
{
    constexpr int ASTRIDE = AF32 ? 144 : 80;       // bytes per A smem row
    constexpr int ATILE   = 128 * ASTRIDE;         // 18432 / 10240
    constexpr int STAGE   = ATILE + 10240;         // + B tile

    const uint32_t sb = smem_u32(dsm);
    const int tid  = threadIdx.x;
    const int lane = tid & 31, wid = tid >> 5;
    const int wm = wid & 1, wn = wid >> 1;         // warp tile: m 64, n 32

    const int lrow = tid >> 1;
    const int lh   = tid & 1;
    const float*  A32 = (const float*)Avoid;
    const __half* A16 = (const __half*)Avoid;
    const __half* bsrc = Wf + (long long)(n0 + lrow) * ND + lh * 16;
    const uint32_t bdst0 = sb + ATILE + lrow * 80 + lh * 32;
    // A loader source/dest
    const float*  asrc32 = A32 + (long long)(m0 + lrow) * ND + lh * 16;
    const __half* asrc16 = A16 + (long long)(m0 + lrow) * ND + lh * 16;
    const uint32_t adst32 = sb + lrow * 144 + lh * 64;
    const uint32_t adst16 = sb + lrow * 80 + lh * 32;

    float acc[4][4][4];
#pragma unroll
    for (int i = 0; i < 4; i++)
#pragma unroll
        for (int j = 0; j < 4; j++)
#pragma unroll
            for (int c = 0; c < 4; c++) acc[i][j][c] = 0.0f;

#define GF_ISSUE(ch, stage) do { \
        if (AF32) { \
            const float* g = asrc32 + (ch) * 32; \
            uint32_t d = adst32 + (stage) * STAGE; \
            CP_ASYNC16(d,      g); \
            CP_ASYNC16(d + 16, g + 4); \
            CP_ASYNC16(d + 32, g + 8); \
            CP_ASYNC16(d + 48, g + 12); \
        } else { \
            const __half* g = asrc16 + (ch) * 32; \
            uint32_t d = adst16 + (stage) * STAGE; \
            CP_ASYNC16(d,      g); \
            CP_ASYNC16(d + 16, g + 8); \
        } \
        { \
            const __half* g = bsrc + (ch) * 32; \
            uint32_t d = bdst0 + (stage) * STAGE; \
            CP_ASYNC16(d,      g); \
            CP_ASYNC16(d + 16, g + 8); \
        } \
        CP_COMMIT(); \
    } while (0)

    GF_ISSUE(0, 0);
    GF_ISSUE(1, 1);

    for (int ch = 0; ch < 64; ch++) {
        const int st = ch & 1;
        CP_WAIT1();
        __syncthreads();
        const uint32_t bbase = sb + st * STAGE + ATILE + (wn * 32) * 80
                             + (lane & 15) * 80 + (lane >> 4) * 16;
        const uint32_t abase16 = sb + st * STAGE + (wm * 64) * 80
                               + (lane & 15) * 80 + (lane >> 4) * 16;
        char* a32base = dsm + st * STAGE;
#pragma unroll
        for (int kk = 0; kk < 2; kk++) {           // two k16 steps per chunk
            uint32_t bh[4][2];
#pragma unroll
            for (int np = 0; np < 2; np++) {
                uint32_t r[4];
                LDSM4(r, bbase + np * 1280 + kk * 32);
                bh[np*2+0][0] = r[0]; bh[np*2+0][1] = r[2];
                bh[np*2+1][0] = r[1]; bh[np*2+1][1] = r[3];
            }
#pragma unroll
            for (int mt = 0; mt < 4; mt++) {
                uint32_t af[4];
                if (AF32) {
                    const int r0 = wm*64 + mt*16 + (lane >> 2);
                    const int c0 = kk*16 + (lane & 3)*2;
                    float2 x0 = *(float2*)(a32base + r0*144 + c0*4);
                    float2 x1 = *(float2*)(a32base + (r0+8)*144 + c0*4);
                    float2 x2 = *(float2*)(a32base + r0*144 + (c0+8)*4);
                    float2 x3 = *(float2*)(a32base + (r0+8)*144 + (c0+8)*4);
                    af[0] = f16x2_pack(x0.x, x0.y);
                    af[1] = f16x2_pack(x1.x, x1.y);
                    af[2] = f16x2_pack(x2.x, x2.y);
                    af[3] = f16x2_pack(x3.x, x3.y);
                } else {
                    LDSM4(af, abase16 + mt * 1280 + kk * 32);
                }
#pragma unroll
                for (int nt = 0; nt < 4; nt++)
                    MMA16816H(acc[mt][nt], af, bh[nt]);
            }
        }
        __syncthreads();
        if (ch + 2 < 64) GF_ISSUE(ch + 2, st);
        else CP_COMMIT();          // keep group-count invariant for WAIT1
    }

    // ---- epilogue ----
    const int r0 = m0 + wm * 64 + (lane >> 2);
    const int c0 = n0 + wn * 32 + (lane & 3) * 2;
#pragma unroll
    for (int nt = 0; nt < 4; nt++) {
        const int c = c0 + nt * 8;
        const float b0 = bias[c], b1 = bias[c + 1];
#pragma unroll
        for (int mt = 0; mt < 4; mt++) {
            const int r = r0 + mt * 16;
            float v00 = acc[mt][nt][0] + b0, v01 = acc[mt][nt][1] + b1;
            float v10 = acc[mt][nt][2] + b0, v11 = acc[mt][nt][3] + b1;
            if (C) {
                *(float2*)&C[(long long)r * ND + c]       = make_float2(v00, v01);
                *(float2*)&C[(long long)(r + 8) * ND + c] = make_float2(v10, v11);
            }
            if (Cf) {
                *(uint32_t*)&Cf[(long long)r * ND + c]       = f16x2_pack(v00, v01);
                *(uint32_t*)&Cf[(long long)(r + 8) * ND + c] = f16x2_pack(v10, v11);
            }
        }
    }
#undef GF_ISSUE
}

#define GF_SMEM32 (2*(128*144 + 10240))   // 57344 (fp32 A)
#define GF_SMEM16 (2*(128*80  + 10240))   // 40960 (fp16 A)

// ---- merged Q/K/V projection from raw fp32 inputs: gridDim.z = 3 ----
__global__ __launch_bounds__(256, 2)
void gemm_qkv_kernel(const float* __restrict__ Xq,
                     const float* __restrict__ Xk,
                     const float* __restrict__ Xv,
                     const __half* __restrict__ whf,
                     const float* __restrict__ bq,
                     const float* __restrict__ bk,
                     const float* __restrict__ bv,
                     __half* __restrict__ qraw, __half* __restrict__ kraw,
                     __half* __restrict__ vf)
{
    extern __shared__ char dsm[];
    const int z = blockIdx.z;
    const float* X = (z == 0) ? Xq : (z == 1) ? Xk : Xv;
    const __half* Wf = whf + (long long)z * ND * ND;
    const float* bias = (z == 0) ? bq : (z == 1) ? bk : bv;
    __half* Cf = (z == 0) ? qraw : (z == 1) ? kraw : vf;
    gemm_f16_body<true>(dsm, X, Wf, bias, nullptr, Cf,
                        blockIdx.y * 128, blockIdx.x * 128);
}

// ---- output projection (fp16 A) ----
__global__ __launch_bounds__(256, 2)
void gemm_out_kernel(const __half* __restrict__ Af,
                     const __half* __restrict__ Wf,
                     const float* __restrict__ bias,
                     float* __restrict__ C)
{
    extern __shared__ char dsm[];
    gemm_f16_body<false>(dsm, Af, Wf, bias, C, nullptr,
                         blockIdx.y * 128, blockIdx.x * 128);
}

// ============================================================================
// rope_all: table-driven rotation, fp16 in/out. z=0: Q (scaled), z=1: K.
// Thread handles 2 adjacent i values (2 pairs).
// ============================================================================
__global__ void rope_all_kernel(const __half* __restrict__ Qr,
                                const __half* __restrict__ Kr,
                                const float* __restrict__ tab,
                                __half* __restrict__ Qo,
                                __half* __restrict__ Ko)
{
    const __half* X = blockIdx.z ? Kr : Qr;
    __half* Y = blockIdx.z ? Ko : Qo;
    const float scale = blockIdx.z ? 1.0f : 0.08838834764831845f;
    int idx = blockIdx.x * blockDim.x + threadIdx.x;  // NM * NH * 32
    int i2  = idx & 31;             // pair of i: i = i2*2, i2*2+1
    int h   = (idx >> 5) & (NH - 1);
    int row = idx >> 9;
    int s   = row & (NS - 1);
    float4 t = *(const float4*)(tab + (s*64 + i2*2) * 2);  // cs0,sn0,cs1,sn1
    long long off = (long long)row * ND + h * HD + i2*2;
    __half2 xa = *(const __half2*)(X + off);
    __half2 xb = *(const __half2*)(X + off + 64);
    float x1a = __half2float(xa.x), x1b = __half2float(xa.y);
    float x2a = __half2float(xb.x), x2b = __half2float(xb.y);
    *(uint32_t*)(Y + off)      = f16x2_pack((x1a*t.x - x2a*t.y) * scale,
                                            (x1b*t.z - x2b*t.w) * scale);
    *(uint32_t*)(Y + off + 64) = f16x2_pack((x2a*t.x + x1a*t.y) * scale,
                                            (x2b*t.z + x1b*t.w) * scale);
}

// ============================================================================
// Causal flash attention on mma.sync, fully 1-pass fp16 (unchanged).
// ============================================================================
#define AT_RS    272
#define AT_TSIZE (64*AT_RS)
#define AT_STAGE (2*AT_TSIZE)
#define AT_SMEM  (2*AT_STAGE)              // 69632

__global__ __launch_bounds__(256)
void attn_mma_kernel(const __half* __restrict__ qf,
                     const __half* __restrict__ kf,
                     const __half* __restrict__ vf,
                     __half* __restrict__ of)
{
    extern __shared__ char dsm[];
    const uint32_t sb = smem_u32(dsm);
    const int tid  = threadIdx.x;
    const int lane = tid & 31, w = tid >> 5;
    const int qt = (NS/128 - 1) - blockIdx.x;   // heavy tiles first
    const int h  = blockIdx.y;
    const int b  = blockIdx.z;
    const int q0 = qt * 128;
    const long long gbase = (long long)b * NS * ND + h * HD;

    // ---- stage Q (128 rows) into stage-0 region; consumed to regs ----
    {
        int r = tid & 127;
        const __half* src = qf + gbase + (long long)(q0 + r) * ND + (tid >> 7) * 64;
        uint32_t dst = sb + r * AT_RS + (tid >> 7) * 128;
#pragma unroll
        for (int c = 0; c < 8; c++) CP_ASYNC16(dst + c*16, src + c*8);
        CP_COMMIT();
        CP_WAIT0();
        __syncthreads();
    }

    uint32_t qfr[8][4];
    {
        uint32_t qaddr = sb + (w*16 + (lane & 15)) * AT_RS + (lane >> 4) * 16;
#pragma unroll
        for (int kc = 0; kc < 8; kc++)
            LDSM4(qfr[kc], qaddr + kc*32);
    }
    __syncthreads();

    const __half* kvsrc = nullptr;
    uint32_t kvdst = 0;
    const bool loader = (tid < 128);
    if (loader) {
        kvsrc = ((tid < 64) ? kf : vf) + gbase + (long long)(tid & 63) * ND;
        kvdst = sb + (tid >> 6) * AT_TSIZE + (tid & 63) * AT_RS;
    }

#define AT_ISSUE(jt, st) do { \
        if (loader) { \
            const __half* g = kvsrc + (long long)(jt) * 64 * ND; \
            uint32_t d = kvdst + (st) * AT_STAGE; \
            _Pragma("unroll") \
            for (int c = 0; c < 16; c++) CP_ASYNC16(d + c*16, g + c*8); \
        } \
        CP_COMMIT(); \
    } while (0)

    const int njt = 2*qt + 2;
    AT_ISSUE(0, 0);
    AT_ISSUE(1, 1);

    float m0v = -1e30f, m1v = -1e30f, l0 = 0.0f, l1 = 0.0f;
    float od[16][4];
#pragma unroll
    for (int nd = 0; nd < 16; nd++)
#pragma unroll
        for (int c = 0; c < 4; c++) od[nd][c] = 0.0f;

    for (int jt = 0; jt < njt; jt++) {
        const int st = jt & 1;
        CP_WAIT1();
        __syncthreads();
        const uint32_t kbase = sb + st * AT_STAGE;
        const uint32_t vbase = kbase + AT_TSIZE;

        float sc[8][4];
#pragma unroll
        for (int n = 0; n < 8; n++)
#pragma unroll
            for (int c = 0; c < 4; c++) sc[n][c] = 0.0f;

#pragma unroll
        for (int kc = 0; kc < 8; kc++) {
#pragma unroll
            for (int ng = 0; ng < 4; ng++) {
                uint32_t rk[4];
                LDSM4(rk, kbase + (ng*16 + (lane & 15)) * AT_RS
                          + kc*32 + (lane >> 4) * 16);
                uint32_t b0[2] = {rk[0], rk[2]}, b1[2] = {rk[1], rk[3]};
                MMA16816H(sc[2*ng],   qfr[kc], b0);
                MMA16816H(sc[2*ng+1], qfr[kc], b1);
            }
        }

        if (jt >= njt - 2) {
            const int qrow = q0 + w*16 + (lane >> 2);
            const int kc0  = jt*64 + (lane & 3)*2;
#pragma unroll
            for (int n = 0; n < 8; n++) {
                int kcol = kc0 + n*8;
                if (kcol     > qrow)     sc[n][0] = -1e30f;
                if (kcol + 1 > qrow)     sc[n][1] = -1e30f;
                if (kcol     > qrow + 8) sc[n][2] = -1e30f;
                if (kcol + 1 > qrow + 8) sc[n][3] = -1e30f;
            }
        }

        float mx0 = -1e30f, mx1 = -1e30f;
#pragma unroll
        for (int n = 0; n < 8; n++) {
            mx0 = fmaxf(mx0, fmaxf(sc[n][0], sc[n][1]));
            mx1 = fmaxf(mx1, fmaxf(sc[n][2], sc[n][3]));
        }
        mx0 = fmaxf(mx0, __shfl_xor_sync(0xffffffffu, mx0, 1));
        mx0 = fmaxf(mx0, __shfl_xor_sync(0xffffffffu, mx0, 2));
        mx1 = fmaxf(mx1, __shfl_xor_sync(0xffffffffu, mx1, 1));
        mx1 = fmaxf(mx1, __shfl_xor_sync(0xffffffffu, mx1, 2));
        float mn0 = fmaxf(m0v, mx0), mn1 = fmaxf(m1v, mx1);
        float corr0 = __expf(m0v - mn0), corr1 = __expf(m1v - mn1);
        float ps0 = 0.0f, ps1 = 0.0f;
#pragma unroll
        for (int n = 0; n < 8; n++) {
            sc[n][0] = __expf(sc[n][0] - mn0);
            sc[n][1] = __expf(sc[n][1] - mn0);
            sc[n][2] = __expf(sc[n][2] - mn1);
            sc[n][3] = __expf(sc[n][3] - mn1);
            ps0 += sc[n][0] + sc[n][1];
            ps1 += sc[n][2] + sc[n][3];
        }
        ps0 += __shfl_xor_sync(0xffffffffu, ps0, 1);
        ps0 += __shfl_xor_sync(0xffffffffu, ps0, 2);
        ps1 += __shfl_xor_sync(0xffffffffu, ps1, 1);
        ps1 += __shfl_xor_sync(0xffffffffu, ps1, 2);
        l0 = l0 * corr0 + ps0;  m0v = mn0;
        l1 = l1 * corr1 + ps1;  m1v = mn1;
#pragma unroll
        for (int nd = 0; nd < 16; nd++) {
            od[nd][0] *= corr0; od[nd][1] *= corr0;
            od[nd][2] *= corr1; od[nd][3] *= corr1;
        }

        uint32_t pa[4][4];
#pragma unroll
        for (int kc2 = 0; kc2 < 4; kc2++) {
            const int n0i = 2*kc2, n1i = 2*kc2 + 1;
            pa[kc2][0] = f16x2_pack(sc[n0i][0], sc[n0i][1]);
            pa[kc2][1] = f16x2_pack(sc[n0i][2], sc[n0i][3]);
            pa[kc2][2] = f16x2_pack(sc[n1i][0], sc[n1i][1]);
            pa[kc2][3] = f16x2_pack(sc[n1i][2], sc[n1i][3]);
        }

#pragma unroll
        for (int d0 = 0; d0 < 8; d0++) {
#pragma unroll
            for (int kc2 = 0; kc2 < 4; kc2++) {
                uint32_t rv[4];
                LDSM4T(rv, vbase + (kc2*16 + (lane & 15)) * AT_RS
                           + d0*32 + (lane >> 4) * 16);
                uint32_t b0[2] = {rv[0], rv[1]}, b1[2] = {rv[2], rv[3]};
                MMA16816H(od[2*d0],   pa[kc2], b0);
                MMA16816H(od[2*d0+1], pa[kc2], b1);
            }
        }

        __syncthreads();
        if (jt + 2 < njt) AT_ISSUE(jt + 2, st);
        else CP_COMMIT();          // keep group-count invariant for WAIT1
    }

    const float i0 = 1.0f / l0, i1 = 1.0f / l1;
    const long long row0 = (long long)(b*NS + q0 + w*16 + (lane >> 2)) * ND + h * HD;
    const long long row1 = row0 + 8ll * ND;
#pragma unroll
    for (int nd = 0; nd < 16; nd++) {
        const int d = nd*8 + (lane & 3)*2;
        *(uint32_t*)&of[row0 + d] = f16x2_pack(od[nd][0]*i0, od[nd][1]*i0);
        *(uint32_t*)&of[row1 + d] = f16x2_pack(od[nd][2]*i1, od[nd][3]*i1);
    }
#undef AT_ISSUE
}

// ============================================================================
extern "C" void kernel_launch(void* const* d_in, const int* in_sizes, int n_in,
                              void* d_out, int out_size)
{
    (void)in_sizes; (void)n_in; (void)out_size;
    const float* queries = (const float*)d_in[0];
    const float* keys    = (const float*)d_in[1];
    const float* values  = (const float*)d_in[2];
    const float* Wq = (const float*)d_in[3];
    const float* bq = (const float*)d_in[4];
    const float* Wk = (const float*)d_in[5];
    const float* bk = (const float*)d_in[6];
    const float* Wv = (const float*)d_in[7];
    const float* bv = (const float*)d_in[8];
    const float* Wo = (const float*)d_in[9];
    const float* bo = (const float*)d_in[10];
    float* out = (float*)d_out;

    __half *whf, *qraw, *kraw, *of, *qf, *kf, *vf;
    float* tab;
    cudaGetSymbolAddress((void**)&whf,  g_whf);
    cudaGetSymbolAddress((void**)&qraw, g_qraw);
    cudaGetSymbolAddress((void**)&kraw, g_kraw);
    cudaGetSymbolAddress((void**)&of,   g_of);
    cudaGetSymbolAddress((void**)&qf,   g_qf);
    cudaGetSymbolAddress((void**)&kf,   g_kf);
    cudaGetSymbolAddress((void**)&vf,   g_vf);
    cudaGetSymbolAddress((void**)&tab,  g_tab);

    cudaFuncSetAttribute(gemm_qkv_kernel,
                         cudaFuncAttributeMaxDynamicSharedMemorySize, GF_SMEM32);
    cudaFuncSetAttribute(gemm_out_kernel,
                         cudaFuncAttributeMaxDynamicSharedMemorySize, GF_SMEM16);
    cudaFuncSetAttribute(attn_mma_kernel,
                         cudaFuncAttributeMaxDynamicSharedMemorySize, AT_SMEM);

    // ---- weight transpose+convert (one launch, z=4) ----
    dim3 gw(ND/32, ND/32, 4), bw(32, 8);
    conv_w_all_kernel<<<gw, bw>>>(Wq, Wk, Wv, Wo, whf);

    // ---- rope table ----
    tab_kernel<<<NS*64/256, 256>>>(tab);

    // ---- Q/K/V projections straight from fp32 inputs (one launch, z=3) ----
    dim3 gqkv(ND/128, NM/128, 3);
    gemm_qkv_kernel<<<gqkv, 256, GF_SMEM32>>>(queries, keys, values, whf,
                                              bq, bk, bv, qraw, kraw, vf);

    // ---- RoPE (table-driven, fp16 I/O; one launch, z=2) ----
    int nrope2 = NM * NH * 32;
    rope_all_kernel<<<dim3(nrope2/256, 1, 2), 256>>>(qraw, kraw, tab, qf, kf);

    // ---- attention (fully 1-pass fp16) ----
    dim3 ga(NS/128, NH, NB);
    attn_mma_kernel<<<ga, 256, AT_SMEM>>>(qf, kf, vf, of);

    // ---- output projection ----
    dim3 gtg(ND/128, NM/128);
    gemm_out_kernel<<<gtg, 256, GF_SMEM16>>>(of, whf + 3ll*ND*ND, bo, out);
}

// round 17
// speedup vs baseline: 1.3781x; 1.3781x over previous
#include <cuda_runtime.h>
#include <cuda_bf16.h>
#include <cuda_fp16.h>
#include <cstdint>
#include <math.h>

#define NB 2
#define NS 2048
#define ND 2048
#define NH 16
#define HD 128
#define NM (NB*NS)   // 4096 rows

// ---- scratch (static device arrays; no allocation allowed) ----
__device__ __half g_whf[4ll*ND*ND];              // W^T fp16, [N][K] K-major
__device__ __half g_af[3ll*NM*ND];               // fp16 activations (q,k,v inputs)
__device__ __half g_qraw[(long long)NM*ND];      // Q proj fp16 (pre-rope)
__device__ __half g_kraw[(long long)NM*ND];      // K proj fp16 (pre-rope)
__device__ __half g_of[(long long)NM*ND];        // attention O fp16
__device__ __half g_qf[(long long)NM*ND];        // roped Q fp16 (scaled)
__device__ __half g_kf[(long long)NM*ND];        // roped K fp16
__device__ __half g_vf[(long long)NM*ND];        // V proj fp16
__device__ float  g_tab[NS*64*2];                // rope (cos,sin) table

__device__ __forceinline__ uint32_t smem_u32(const void* p) {
    uint32_t a;
    asm("{ .reg .u64 t; cvta.to.shared.u64 t, %1; cvt.u32.u64 %0, t; }"
        : "=r"(a) : "l"(p));
    return a;
}

// ---- base-target tensor core primitives (sm_80-class, valid on compute_103) ----
#define LDSM4(r, addr) \
    asm volatile("ldmatrix.sync.aligned.m8n8.x4.shared.b16 {%0,%1,%2,%3}, [%4];" \
        : "=r"((r)[0]), "=r"((r)[1]), "=r"((r)[2]), "=r"((r)[3]) : "r"(addr))

#define LDSM4T(r, addr) \
    asm volatile("ldmatrix.sync.aligned.m8n8.x4.trans.shared.b16 {%0,%1,%2,%3}, [%4];" \
        : "=r"((r)[0]), "=r"((r)[1]), "=r"((r)[2]), "=r"((r)[3]) : "r"(addr))

#define MMA16816H(d, a, b) \
    asm volatile("mma.sync.aligned.m16n8k16.row.col.f32.f16.f16.f32 " \
        "{%0,%1,%2,%3}, {%4,%5,%6,%7}, {%8,%9}, {%0,%1,%2,%3};" \
        : "+f"((d)[0]), "+f"((d)[1]), "+f"((d)[2]), "+f"((d)[3]) \
        : "r"((a)[0]), "r"((a)[1]), "r"((a)[2]), "r"((a)[3]), \
          "r"((b)[0]), "r"((b)[1]))

#define CP_ASYNC16(dst, src) \
    asm volatile("cp.async.cg.shared.global [%0], [%1], 16;" \
                 :: "r"(dst), "l"(src) : "memory")
#define CP_COMMIT()  asm volatile("cp.async.commit_group;" ::: "memory")
#define CP_WAIT1()   asm volatile("cp.async.wait_group 1;" ::: "memory")
#define CP_WAIT0()   asm volatile("cp.async.wait_group 0;" ::: "memory")

__device__ __forceinline__ uint32_t f16x2_pack(float lo, float hi) {
    __half2 v = __floats2half2_rn(lo, hi);
    return *reinterpret_cast<uint32_t*>(&v);
}

// ============================================================================
// conv_a_all: fp32 -> fp16 for queries/keys/values in one launch (z selects)
// ============================================================================
__global__ void conv_a_all_kernel(const float* __restrict__ Xq,
                                  const float* __restrict__ Xk,
                                  const float* __restrict__ Xv,
                                  __half* __restrict__ Y)
{
    const float* X = (blockIdx.z == 0) ? Xq : (blockIdx.z == 1) ? Xk : Xv;
    __half* Yz = Y + (long long)blockIdx.z * NM * ND;
    long long idx = (long long)(blockIdx.x * blockDim.x + threadIdx.x) * 8;
    float4 a = *(const float4*)(X + idx);
    float4 b = *(const float4*)(X + idx + 4);
    uint4 o;
    o.x = f16x2_pack(a.x, a.y);
    o.y = f16x2_pack(a.z, a.w);
    o.z = f16x2_pack(b.x, b.y);
    o.w = f16x2_pack(b.z, b.w);
    *(uint4*)(Yz + idx) = o;
}

// ============================================================================
// conv_w_all: 4 weight matrices, one launch (z selects). Transpose to [N][K].
// ============================================================================
__global__ void conv_w_all_kernel(const float* __restrict__ W0,
                                  const float* __restrict__ W1,
                                  const float* __restrict__ W2,
                                  const float* __restrict__ W3,
                                  __half* __restrict__ Wt)
{
    const float* Wz = (blockIdx.z == 0) ? W0 : (blockIdx.z == 1) ? W1
                    : (blockIdx.z == 2) ? W2 : W3;
    __half* Wtz = Wt + (long long)blockIdx.z * ND * ND;
    __shared__ float t[32][33];
    int n0 = blockIdx.x * 32, k0 = blockIdx.y * 32;
    int tx = threadIdx.x, ty = threadIdx.y;
    for (int r = ty; r < 32; r += 8)
        t[r][tx] = Wz[(long long)(k0 + r) * ND + n0 + tx];
    __syncthreads();
    for (int r = ty; r < 32; r += 8)
        Wtz[(long long)(n0 + r) * ND + k0 + tx] = __float2half_rn(t[tx][r]);
}

// ============================================================================
// tab_kernel: rope (cos,sin) table, [s][i] -> (cos, sin)
// ============================================================================
__global__ void tab_kernel(float* __restrict__ tab)
{
    int idx = blockIdx.x * blockDim.x + threadIdx.x;   // NS*64
    int i = idx & 63, s = idx >> 6;
    float ang = (float)s * powf(10000.0f, -(float)i / 64.0f);
    float sn, cs;
    sincosf(ang, &sn, &cs);
    tab[idx*2]   = cs;
    tab[idx*2+1] = sn;
}

// ============================================================================
// 1-pass fp16 GEMM body: C = A(f16) @ W^T(f16) + bias
// Outputs fp32 C and/or fp16 Cf (either may be null).
// CTA 128x128, 8 warps (warp tile 64x32), K-chunk 32 f16, double buffer.
// smem rows: 64B payload, 80B stride (conflict-free ldmatrix).
// ============================================================================
#define GF_STAGE 20480                    // 2 matrices * 128 rows * 80B
#define GF_SMEM  (2*GF_STAGE)             // 40960

__device__ __forceinline__
void gemm_f16_body(char* dsm,
                   const __half* __restrict__ Af,
                   const __half* __restrict__ Wf,
                   const float* __restrict__ bias,
                   float* __restrict__ C,
                   __half* __restrict__ Cf,
                   int m0, int n0)
{
    const uint32_t sb = smem_u32(dsm);
    const int tid  = threadIdx.x;
    const int lane = tid & 31, wid = tid >> 5;
    const int wm = wid & 1, wn = wid >> 1;      // warp tile: m 64, n 32

    const int lrow = tid >> 1;
    const int lc   = (tid & 1) * 16;            // elements (32B)
    const __half* gsrc[2];
    gsrc[0] = Af + (long long)(m0 + lrow) * ND + lc;
    gsrc[1] = Wf + (long long)(n0 + lrow) * ND + lc;
    const uint32_t sdst0 = sb + lrow * 80 + (tid & 1) * 32;

    float acc[4][4][4];
#pragma unroll
    for (int i = 0; i < 4; i++)
#pragma unroll
        for (int j = 0; j < 4; j++)
#pragma unroll
            for (int c = 0; c < 4; c++) acc[i][j][c] = 0.0f;

#define GF_ISSUE(ch, stage) do { \
        uint32_t s0 = sdst0 + (stage) * GF_STAGE; \
        _Pragma("unroll") \
        for (int m = 0; m < 2; m++) { \
            const __half* g = gsrc[m] + (ch) * 32; \
            uint32_t d = s0 + m * 10240; \
            CP_ASYNC16(d, g); \
            CP_ASYNC16(d + 16, g + 8); \
        } \
        CP_COMMIT(); \
    } while (0)

    GF_ISSUE(0, 0);
    GF_ISSUE(1, 1);

    for (int ch = 0; ch < 64; ch++) {
        const int st = ch & 1;
        CP_WAIT1();
        __syncthreads();
        const uint32_t abase = sb + st * GF_STAGE + (wm * 64) * 80
                             + (lane & 15) * 80 + (lane >> 4) * 16;
        const uint32_t bbase = sb + st * GF_STAGE + 10240 + (wn * 32) * 80
                             + (lane & 15) * 80 + (lane >> 4) * 16;
#pragma unroll
        for (int kk = 0; kk < 2; kk++) {        // two k16 steps per 32-elem chunk
            uint32_t bh[4][2];
#pragma unroll
            for (int np = 0; np < 2; np++) {
                uint32_t r[4];
                LDSM4(r, bbase + np * 1280 + kk * 32);
                bh[np*2+0][0] = r[0]; bh[np*2+0][1] = r[2];
                bh[np*2+1][0] = r[1]; bh[np*2+1][1] = r[3];
            }
#pragma unroll
            for (int mt = 0; mt < 4; mt++) {
                uint32_t af[4];
                LDSM4(af, abase + mt * 1280 + kk * 32);
#pragma unroll
                for (int nt = 0; nt < 4; nt++)
                    MMA16816H(acc[mt][nt], af, bh[nt]);
            }
        }
        __syncthreads();
        if (ch + 2 < 64) GF_ISSUE(ch + 2, st);
        else CP_COMMIT();          // keep group-count invariant for WAIT1
    }

    // ---- epilogue ----
    const int r0 = m0 + wm * 64 + (lane >> 2);
    const int c0 = n0 + wn * 32 + (lane & 3) * 2;
#pragma unroll
    for (int nt = 0; nt < 4; nt++) {
        const int c = c0 + nt * 8;
        const float b0 = bias[c], b1 = bias[c + 1];
#pragma unroll
        for (int mt = 0; mt < 4; mt++) {
            const int r = r0 + mt * 16;
            float v00 = acc[mt][nt][0] + b0, v01 = acc[mt][nt][1] + b1;
            float v10 = acc[mt][nt][2] + b0, v11 = acc[mt][nt][3] + b1;
            if (C) {
                *(float2*)&C[(long long)r * ND + c]       = make_float2(v00, v01);
                *(float2*)&C[(long long)(r + 8) * ND + c] = make_float2(v10, v11);
            }
            if (Cf) {
                *(uint32_t*)&Cf[(long long)r * ND + c]       = f16x2_pack(v00, v01);
                *(uint32_t*)&Cf[(long long)(r + 8) * ND + c] = f16x2_pack(v10, v11);
            }
        }
    }
#undef GF_ISSUE
}

// ---- merged Q/K/V projection: gridDim.z = 3 selects matrix; fp16 outputs ----
__global__ __launch_bounds__(256, 2)
void gemm_qkv_kernel(const __half* __restrict__ af,
                     const __half* __restrict__ whf,
                     const float* __restrict__ bq,
                     const float* __restrict__ bk,
                     const float* __restrict__ bv,
                     __half* __restrict__ qraw, __half* __restrict__ kraw,
                     __half* __restrict__ vf)
{
    extern __shared__ char dsm[];
    const int z = blockIdx.z;
    const __half* Af = af + (long long)z * NM * ND;
    const __half* Wf = whf + (long long)z * ND * ND;
    const float* bias = (z == 0) ? bq : (z == 1) ? bk : bv;
    __half* Cf = (z == 0) ? qraw : (z == 1) ? kraw : vf;
    gemm_f16_body(dsm, Af, Wf, bias, nullptr, Cf,
                  blockIdx.y * 128, blockIdx.x * 128);
}

// ---- output projection (fp32 out) ----
__global__ __launch_bounds__(256, 2)
void gemm_out_kernel(const __half* __restrict__ Af,
                     const __half* __restrict__ Wf,
                     const float* __restrict__ bias,
                     float* __restrict__ C)
{
    extern __shared__ char dsm[];
    gemm_f16_body(dsm, Af, Wf, bias, C, nullptr,
                  blockIdx.y * 128, blockIdx.x * 128);
}

// ============================================================================
// rope_all: table-driven rotation, fp16 in/out. z=0: Q (scaled), z=1: K.
// Thread handles 2 adjacent i values (2 pairs).
// ============================================================================
__global__ void rope_all_kernel(const __half* __restrict__ Qr,
                                const __half* __restrict__ Kr,
                                const float* __restrict__ tab,
                                __half* __restrict__ Qo,
                                __half* __restrict__ Ko)
{
    const __half* X = blockIdx.z ? Kr : Qr;
    __half* Y = blockIdx.z ? Ko : Qo;
    const float scale = blockIdx.z ? 1.0f : 0.08838834764831845f;
    int idx = blockIdx.x * blockDim.x + threadIdx.x;  // NM * NH * 32
    int i2  = idx & 31;             // pair of i: i = i2*2, i2*2+1
    int h   = (idx >> 5) & (NH - 1);
    int row = idx >> 9;
    int s   = row & (NS - 1);
    float4 t = *(const float4*)(tab + (s*64 + i2*2) * 2);  // cs0,sn0,cs1,sn1
    long long off = (long long)row * ND + h * HD + i2*2;
    __half2 xa = *(const __half2*)(X + off);
    __half2 xb = *(const __half2*)(X + off + 64);
    float x1a = __half2float(xa.x), x1b = __half2float(xa.y);
    float x2a = __half2float(xb.x), x2b = __half2float(xb.y);
    *(uint32_t*)(Y + off)      = f16x2_pack((x1a*t.x - x2a*t.y) * scale,
                                            (x1b*t.z - x2b*t.w) * scale);
    *(uint32_t*)(Y + off + 64) = f16x2_pack((x2a*t.x + x1a*t.y) * scale,
                                            (x2b*t.z + x1b*t.w) * scale);
}

// ============================================================================
// Causal flash attention on mma.sync, fully 1-pass fp16 (unchanged from R12).
// ============================================================================
#define AT_RS    272
#define AT_TSIZE (64*AT_RS)
#define AT_STAGE (2*AT_TSIZE)
#define AT_SMEM  (2*AT_STAGE)              // 69632

__global__ __launch_bounds__(256)
void attn_mma_kernel(const __half* __restrict__ qf,
                     const __half* __restrict__ kf,
                     const __half* __restrict__ vf,
                     __half* __restrict__ of)
{
    extern __shared__ char dsm[];
    const uint32_t sb = smem_u32(dsm);
    const int tid  = threadIdx.x;
    const int lane = tid & 31, w = tid >> 5;
    const int qt = (NS/128 - 1) - blockIdx.x;   // heavy tiles first
    const int h  = blockIdx.y;
    const int b  = blockIdx.z;
    const int q0 = qt * 128;
    const long long gbase = (long long)b * NS * ND + h * HD;

    // ---- stage Q (128 rows) into stage-0 region; consumed to regs ----
    {
        int r = tid & 127;
        const __half* src = qf + gbase + (long long)(q0 + r) * ND + (tid >> 7) * 64;
        uint32_t dst = sb + r * AT_RS + (tid >> 7) * 128;
#pragma unroll
        for (int c = 0; c < 8; c++) CP_ASYNC16(dst + c*16, src + c*8);
        CP_COMMIT();
        CP_WAIT0();
        __syncthreads();
    }

    uint32_t qfr[8][4];
    {
        uint32_t qaddr = sb + (w*16 + (lane & 15)) * AT_RS + (lane >> 4) * 16;
#pragma unroll
        for (int kc = 0; kc < 8; kc++)
            LDSM4(qfr[kc], qaddr + kc*32);
    }
    __syncthreads();

    const __half* kvsrc = nullptr;
    uint32_t kvdst = 0;
    const bool loader = (tid < 128);
    if (loader) {
        kvsrc = ((tid < 64) ? kf : vf) + gbase + (long long)(tid & 63) * ND;
        kvdst = sb + (tid >> 6) * AT_TSIZE + (tid & 63) * AT_RS;
    }

#define AT_ISSUE(jt, st) do { \
        if (loader) { \
            const __half* g = kvsrc + (long long)(jt) * 64 * ND; \
            uint32_t d = kvdst + (st) * AT_STAGE; \
            _Pragma("unroll") \
            for (int c = 0; c < 16; c++) CP_ASYNC16(d + c*16, g + c*8); \
        } \
        CP_COMMIT(); \
    } while (0)

    const int njt = 2*qt + 2;
    AT_ISSUE(0, 0);
    AT_ISSUE(1, 1);

    float m0v = -1e30f, m1v = -1e30f, l0 = 0.0f, l1 = 0.0f;
    float od[16][4];
#pragma unroll
    for (int nd = 0; nd < 16; nd++)
#pragma unroll
        for (int c = 0; c < 4; c++) od[nd][c] = 0.0f;

    for (int jt = 0; jt < njt; jt++) {
        const int st = jt & 1;
        CP_WAIT1();
        __syncthreads();
        const uint32_t kbase = sb + st * AT_STAGE;
        const uint32_t vbase = kbase + AT_TSIZE;

        float sc[8][4];
#pragma unroll
        for (int n = 0; n < 8; n++)
#pragma unroll
            for (int c = 0; c < 4; c++) sc[n][c] = 0.0f;

#pragma unroll
        for (int kc = 0; kc < 8; kc++) {
#pragma unroll
            for (int ng = 0; ng < 4; ng++) {
                uint32_t rk[4];
                LDSM4(rk, kbase + (ng*16 + (lane & 15)) * AT_RS
                          + kc*32 + (lane >> 4) * 16);
                uint32_t b0[2] = {rk[0], rk[2]}, b1[2] = {rk[1], rk[3]};
                MMA16816H(sc[2*ng],   qfr[kc], b0);
                MMA16816H(sc[2*ng+1], qfr[kc], b1);
            }
        }

        if (jt >= njt - 2) {
            const int qrow = q0 + w*16 + (lane >> 2);
            const int kc0  = jt*64 + (lane & 3)*2;
#pragma unroll
            for (int n = 0; n < 8; n++) {
                int kcol = kc0 + n*8;
                if (kcol     > qrow)     sc[n][0] = -1e30f;
                if (kcol + 1 > qrow)     sc[n][1] = -1e30f;
                if (kcol     > qrow + 8) sc[n][2] = -1e30f;
                if (kcol + 1 > qrow + 8) sc[n][3] = -1e30f;
            }
        }

        float mx0 = -1e30f, mx1 = -1e30f;
#pragma unroll
        for (int n = 0; n < 8; n++) {
            mx0 = fmaxf(mx0, fmaxf(sc[n][0], sc[n][1]));
            mx1 = fmaxf(mx1, fmaxf(sc[n][2], sc[n][3]));
        }
        mx0 = fmaxf(mx0, __shfl_xor_sync(0xffffffffu, mx0, 1));
        mx0 = fmaxf(mx0, __shfl_xor_sync(0xffffffffu, mx0, 2));
        mx1 = fmaxf(mx1, __shfl_xor_sync(0xffffffffu, mx1, 1));
        mx1 = fmaxf(mx1, __shfl_xor_sync(0xffffffffu, mx1, 2));
        float mn0 = fmaxf(m0v, mx0), mn1 = fmaxf(m1v, mx1);
        float corr0 = __expf(m0v - mn0), corr1 = __expf(m1v - mn1);
        float ps0 = 0.0f, ps1 = 0.0f;
#pragma unroll
        for (int n = 0; n < 8; n++) {
            sc[n][0] = __expf(sc[n][0] - mn0);
            sc[n][1] = __expf(sc[n][1] - mn0);
            sc[n][2] = __expf(sc[n][2] - mn1);
            sc[n][3] = __expf(sc[n][3] - mn1);
            ps0 += sc[n][0] + sc[n][1];
            ps1 += sc[n][2] + sc[n][3];
        }
        ps0 += __shfl_xor_sync(0xffffffffu, ps0, 1);
        ps0 += __shfl_xor_sync(0xffffffffu, ps0, 2);
        ps1 += __shfl_xor_sync(0xffffffffu, ps1, 1);
        ps1 += __shfl_xor_sync(0xffffffffu, ps1, 2);
        l0 = l0 * corr0 + ps0;  m0v = mn0;
        l1 = l1 * corr1 + ps1;  m1v = mn1;
#pragma unroll
        for (int nd = 0; nd < 16; nd++) {
            od[nd][0] *= corr0; od[nd][1] *= corr0;
            od[nd][2] *= corr1; od[nd][3] *= corr1;
        }

        uint32_t pa[4][4];
#pragma unroll
        for (int kc2 = 0; kc2 < 4; kc2++) {
            const int n0i = 2*kc2, n1i = 2*kc2 + 1;
            pa[kc2][0] = f16x2_pack(sc[n0i][0], sc[n0i][1]);
            pa[kc2][1] = f16x2_pack(sc[n0i][2], sc[n0i][3]);
            pa[kc2][2] = f16x2_pack(sc[n1i][0], sc[n1i][1]);
            pa[kc2][3] = f16x2_pack(sc[n1i][2], sc[n1i][3]);
        }

#pragma unroll
        for (int d0 = 0; d0 < 8; d0++) {
#pragma unroll
            for (int kc2 = 0; kc2 < 4; kc2++) {
                uint32_t rv[4];
                LDSM4T(rv, vbase + (kc2*16 + (lane & 15)) * AT_RS
                           + d0*32 + (lane >> 4) * 16);
                uint32_t b0[2] = {rv[0], rv[1]}, b1[2] = {rv[2], rv[3]};
                MMA16816H(od[2*d0],   pa[kc2], b0);
                MMA16816H(od[2*d0+1], pa[kc2], b1);
            }
        }

        __syncthreads();
        if (jt + 2 < njt) AT_ISSUE(jt + 2, st);
        else CP_COMMIT();          // keep group-count invariant for WAIT1
    }

    const float i0 = 1.0f / l0, i1 = 1.0f / l1;
    const long long row0 = (long long)(b*NS + q0 + w*16 + (lane >> 2)) * ND + h * HD;
    const long long row1 = row0 + 8ll * ND;
#pragma unroll
    for (int nd = 0; nd < 16; nd++) {
        const int d = nd*8 + (lane & 3)*2;
        *(uint32_t*)&of[row0 + d] = f16x2_pack(od[nd][0]*i0, od[nd][1]*i0);
        *(uint32_t*)&of[row1 + d] = f16x2_pack(od[nd][2]*i1, od[nd][3]*i1);
    }
#undef AT_ISSUE
}

// ============================================================================
extern "C" void kernel_launch(void* const* d_in, const int* in_sizes, int n_in,
                              void* d_out, int out_size)
{
    (void)in_sizes; (void)n_in; (void)out_size;
    const float* queries = (const float*)d_in[0];
    const float* keys    = (const float*)d_in[1];
    const float* values  = (const float*)d_in[2];
    const float* Wq = (const float*)d_in[3];
    const float* bq = (const float*)d_in[4];
    const float* Wk = (const float*)d_in[5];
    const float* bk = (const float*)d_in[6];
    const float* Wv = (const float*)d_in[7];
    const float* bv = (const float*)d_in[8];
    const float* Wo = (const float*)d_in[9];
    const float* bo = (const float*)d_in[10];
    float* out = (float*)d_out;

    __half *whf, *af, *qraw, *kraw, *of, *qf, *kf, *vf;
    float* tab;
    cudaGetSymbolAddress((void**)&whf,  g_whf);
    cudaGetSymbolAddress((void**)&af,   g_af);
    cudaGetSymbolAddress((void**)&qraw, g_qraw);
    cudaGetSymbolAddress((void**)&kraw, g_kraw);
    cudaGetSymbolAddress((void**)&of,   g_of);
    cudaGetSymbolAddress((void**)&qf,   g_qf);
    cudaGetSymbolAddress((void**)&kf,   g_kf);
    cudaGetSymbolAddress((void**)&vf,   g_vf);
    cudaGetSymbolAddress((void**)&tab,  g_tab);

    cudaFuncSetAttribute(gemm_qkv_kernel,
                         cudaFuncAttributeMaxDynamicSharedMemorySize, GF_SMEM);
    cudaFuncSetAttribute(gemm_out_kernel,
                         cudaFuncAttributeMaxDynamicSharedMemorySize, GF_SMEM);
    cudaFuncSetAttribute(attn_mma_kernel,
                         cudaFuncAttributeMaxDynamicSharedMemorySize, AT_SMEM);

    // ---- weight transpose+convert (one launch, z=4) ----
    dim3 gw(ND/32, ND/32, 4), bw(32, 8);
    conv_w_all_kernel<<<gw, bw>>>(Wq, Wk, Wv, Wo, whf);

    // ---- rope table ----
    tab_kernel<<<NS*64/256, 256>>>(tab);

    // ---- activation convert (one launch, z=3) ----
    const int nconv = NM*ND/8/256;
    conv_a_all_kernel<<<dim3(nconv, 1, 3), 256>>>(queries, keys, values, af);

    // ---- Q/K/V projections (one launch, z=3; fp16 outputs) ----
    dim3 gqkv(ND/128, NM/128, 3);
    gemm_qkv_kernel<<<gqkv, 256, GF_SMEM>>>(af, whf, bq, bk, bv, qraw, kraw, vf);

    // ---- RoPE (table-driven, fp16 I/O; one launch, z=2) ----
    int nrope2 = NM * NH * 32;
    rope_all_kernel<<<dim3(nrope2/256, 1, 2), 256>>>(qraw, kraw, tab, qf, kf);

    // ---- attention (fully 1-pass fp16) ----
    dim3 ga(NS/128, NH, NB);
    attn_mma_kernel<<<ga, 256, AT_SMEM>>>(qf, kf, vf, of);

    // ---- output projection ----
    dim3 gtg(ND/128, NM/128);
    gemm_out_kernel<<<gtg, 256, GF_SMEM>>>(of, whf + 3ll*ND*ND, bo, out);
}